// round 1
// baseline (speedup 1.0000x reference)
#include <cuda_runtime.h>
#include <math.h>

#define LQ 1024
#define BB 16
#define FF 512
#define HH 8
#define KK 64
#define TEMPS 30.0f

// Scratch: normalized projections, layout [B][H][L][K] so each (b,h) matrix is contiguous.
__device__ float g_wq[(size_t)BB * HH * LQ * KK];
__device__ float g_wk[(size_t)BB * HH * LQ * KK];

__device__ __forceinline__ void fma4(float4& a, float p, const float4& v) {
    a.x = fmaf(p, v.x, a.x);
    a.y = fmaf(p, v.y, a.y);
    a.z = fmaf(p, v.z, a.z);
    a.w = fmaf(p, v.w, a.w);
}

// ---------------------------------------------------------------------------
// Kernel 1: C[M,512] = X[M,512] @ W[512,512]^T + bias, then L2-normalize each
// 64-wide head group. Tile 64x64, BK=16, 256 threads, 4x4 per thread.
// grid = (M/64, 8) ; blockIdx.y == head (N-tile of 64 == one head exactly).
// Output layout: [B][H][L][64], row m = q*B + b.
// ---------------------------------------------------------------------------
__global__ __launch_bounds__(256) void proj_kernel(const float* __restrict__ X,
                                                   const float* __restrict__ W,
                                                   const float* __restrict__ bias,
                                                   float* __restrict__ outp) {
    __shared__ float As[16][68];
    __shared__ float Bs[16][68];
    __shared__ float Cs[64][68];
    __shared__ float scl[64];

    const int tid = threadIdx.x;
    const int tx = tid & 15, ty = tid >> 4;
    const int m0 = blockIdx.x * 64;
    const int h = blockIdx.y;
    const int n0 = h * 64;

    float acc[4][4] = {};

    const int lrow = tid >> 2;        // 0..63
    const int lk4 = (tid & 3) * 4;    // 0,4,8,12

    const float* Xp = X + (size_t)(m0 + lrow) * FF + lk4;
    const float* Wp = W + (size_t)(n0 + lrow) * FF + lk4;

    for (int k0 = 0; k0 < FF; k0 += 16) {
        float4 a = *(const float4*)(Xp + k0);
        float4 w = *(const float4*)(Wp + k0);
        As[lk4 + 0][lrow] = a.x; As[lk4 + 1][lrow] = a.y;
        As[lk4 + 2][lrow] = a.z; As[lk4 + 3][lrow] = a.w;
        Bs[lk4 + 0][lrow] = w.x; Bs[lk4 + 1][lrow] = w.y;
        Bs[lk4 + 2][lrow] = w.z; Bs[lk4 + 3][lrow] = w.w;
        __syncthreads();
#pragma unroll
        for (int k = 0; k < 16; k++) {
            float4 av = *(const float4*)&As[k][ty * 4];
            float4 bw = *(const float4*)&Bs[k][tx * 4];
            float aa[4] = {av.x, av.y, av.z, av.w};
            float ww[4] = {bw.x, bw.y, bw.z, bw.w};
#pragma unroll
            for (int i = 0; i < 4; i++)
#pragma unroll
                for (int j = 0; j < 4; j++)
                    acc[i][j] = fmaf(aa[i], ww[j], acc[i][j]);
        }
        __syncthreads();
    }

    // bias + stage tile to smem
    float bj[4];
#pragma unroll
    for (int j = 0; j < 4; j++) bj[j] = bias[n0 + tx * 4 + j];
#pragma unroll
    for (int i = 0; i < 4; i++)
#pragma unroll
        for (int j = 0; j < 4; j++)
            Cs[ty * 4 + i][tx * 4 + j] = acc[i][j] + bj[j];
    __syncthreads();

    // per-row (= per (q,b,h) vector) L2 norm, matching torch F.normalize eps
    if (tid < 64) {
        float ss = 0.f;
#pragma unroll 8
        for (int c = 0; c < 64; c++) {
            float v = Cs[tid][c];
            ss = fmaf(v, v, ss);
        }
        float nrm = sqrtf(ss);
        scl[tid] = 1.0f / fmaxf(nrm, 1e-12f);
    }
    __syncthreads();

#pragma unroll
    for (int i = 0; i < 4; i++) {
        int m = m0 + ty * 4 + i;
        int q = m >> 4;        // B = 16
        int b = m & 15;
        float s = scl[ty * 4 + i];
        float4 o;
        o.x = Cs[ty * 4 + i][tx * 4 + 0] * s;
        o.y = Cs[ty * 4 + i][tx * 4 + 1] * s;
        o.z = Cs[ty * 4 + i][tx * 4 + 2] * s;
        o.w = Cs[ty * 4 + i][tx * 4 + 3] * s;
        *(float4*)(outp + (((size_t)(b * HH + h) * LQ + q) * KK) + tx * 4) = o;
    }
}

// ---------------------------------------------------------------------------
// Kernel 2: attention for one (b, h, 32-row q-tile).
//   Phase A: S[32,1024] = Q[32,64] @ K^T * TEMP  (scores kept in smem)
//   Phase B: exact softmax per row (exp stored back, 1/sum kept in inv[])
//   Phase C: O[32,512] = P @ V_b, inv folded into epilogue.
// smem: scores 128KB + Q 8KB + K-tile 17KB + inv.
// ---------------------------------------------------------------------------
__global__ __launch_bounds__(256, 1) void attn_kernel(const float* __restrict__ value,
                                                      float* __restrict__ out) {
    extern __shared__ float sm[];
    float* sc = sm;                       // 32*1024
    float* Qs = sm + 32 * 1024;           // 32*64
    float* Kst = Qs + 32 * 64;            // [k][s] 64*68
    float* inv = Kst + 64 * 68;           // 32

    const int tid = threadIdx.x;
    const int q0 = blockIdx.x * 32;
    const int h = blockIdx.y;
    const int b = blockIdx.z;

    const float* qbase = g_wq + ((size_t)(b * HH + h) * LQ + q0) * KK;
    const float* kbase = g_wk + (size_t)(b * HH + h) * LQ * KK;

    // load Q tile (2048 floats)
    for (int i = tid; i < 32 * 64 / 4; i += 256)
        ((float4*)Qs)[i] = ((const float4*)qbase)[i];

    const int tx = tid & 15, ty = tid >> 4;

    // ---------------- Phase A: scores ----------------
    for (int st = 0; st < 16; st++) {
        const float* kp = kbase + (size_t)st * 64 * KK;
        const int sr = tid >> 2;
        const int kb = (tid & 3) * 16;
#pragma unroll
        for (int u = 0; u < 4; u++) {
            float4 v = *(const float4*)(kp + sr * 64 + kb + u * 4);
            Kst[(kb + u * 4 + 0) * 68 + sr] = v.x;
            Kst[(kb + u * 4 + 1) * 68 + sr] = v.y;
            Kst[(kb + u * 4 + 2) * 68 + sr] = v.z;
            Kst[(kb + u * 4 + 3) * 68 + sr] = v.w;
        }
        __syncthreads();

        float acc0[4] = {}, acc1[4] = {};
        const float* qr0 = Qs + (ty * 2) * 64;
        const float* qr1 = qr0 + 64;
#pragma unroll 16
        for (int k = 0; k < 64; k++) {
            float qa = qr0[k];
            float qb = qr1[k];
            float4 kv = *(const float4*)&Kst[k * 68 + tx * 4];
            acc0[0] = fmaf(qa, kv.x, acc0[0]);
            acc0[1] = fmaf(qa, kv.y, acc0[1]);
            acc0[2] = fmaf(qa, kv.z, acc0[2]);
            acc0[3] = fmaf(qa, kv.w, acc0[3]);
            acc1[0] = fmaf(qb, kv.x, acc1[0]);
            acc1[1] = fmaf(qb, kv.y, acc1[1]);
            acc1[2] = fmaf(qb, kv.z, acc1[2]);
            acc1[3] = fmaf(qb, kv.w, acc1[3]);
        }
        float4 s0 = make_float4(acc0[0] * TEMPS, acc0[1] * TEMPS, acc0[2] * TEMPS, acc0[3] * TEMPS);
        float4 s1 = make_float4(acc1[0] * TEMPS, acc1[1] * TEMPS, acc1[2] * TEMPS, acc1[3] * TEMPS);
        *(float4*)&sc[(ty * 2) * 1024 + st * 64 + tx * 4] = s0;
        *(float4*)&sc[(ty * 2 + 1) * 1024 + st * 64 + tx * 4] = s1;
        __syncthreads();
    }

    // ---------------- Phase B: softmax (one warp : 4 rows) ----------------
    const int w = tid >> 5, lane = tid & 31;
#pragma unroll
    for (int i = 0; i < 4; i++) {
        const int r = w * 4 + i;
        float* row = sc + r * 1024;
        float m = -1e30f;
        for (int s = lane; s < 1024; s += 32) m = fmaxf(m, row[s]);
#pragma unroll
        for (int o = 16; o; o >>= 1) m = fmaxf(m, __shfl_xor_sync(0xFFFFFFFFu, m, o));
        float sum = 0.f;
        for (int s = lane; s < 1024; s += 32) {
            float e = __expf(row[s] - m);
            row[s] = e;
            sum += e;
        }
#pragma unroll
        for (int o = 16; o; o >>= 1) sum += __shfl_xor_sync(0xFFFFFFFFu, sum, o);
        if (lane == 0) inv[r] = 1.0f / sum;
    }
    __syncthreads();

    // ---------------- Phase C: O = P @ V ----------------
    // warp rg owns rows rg*4..rg*4+3 ; lane owns cols lane*4 + j*128 (j<4)
    const int rg = w;
    const float* vcol = value + (size_t)b * FF + lane * 4;
    const float* prow = sc + (size_t)(rg * 4) * 1024;

    float4 acc[4][4];
#pragma unroll
    for (int i = 0; i < 4; i++)
#pragma unroll
        for (int j = 0; j < 4; j++) acc[i][j] = make_float4(0.f, 0.f, 0.f, 0.f);

#pragma unroll 4
    for (int s = 0; s < LQ; s++) {
        const float* vp = vcol + (size_t)s * (BB * FF);
        float4 v0 = *(const float4*)(vp);
        float4 v1 = *(const float4*)(vp + 128);
        float4 v2 = *(const float4*)(vp + 256);
        float4 v3 = *(const float4*)(vp + 384);
#pragma unroll
        for (int i = 0; i < 4; i++) {
            float p = prow[i * 1024 + s];
            fma4(acc[i][0], p, v0);
            fma4(acc[i][1], p, v1);
            fma4(acc[i][2], p, v2);
            fma4(acc[i][3], p, v3);
        }
    }

#pragma unroll
    for (int i = 0; i < 4; i++) {
        const int q = q0 + rg * 4 + i;
        const float iv = inv[rg * 4 + i];
        float* op = out + ((size_t)q * BB + b) * (HH * FF) + h * FF + lane * 4;
#pragma unroll
        for (int j = 0; j < 4; j++) {
            float4 o = acc[i][j];
            o.x *= iv; o.y *= iv; o.z *= iv; o.w *= iv;
            *(float4*)(op + j * 128) = o;
        }
    }
}

// ---------------------------------------------------------------------------
extern "C" void kernel_launch(void* const* d_in, const int* in_sizes, int n_in,
                              void* d_out, int out_size) {
    const float* query = (const float*)d_in[0];  // [1024,16,512]
    const float* key   = (const float*)d_in[1];  // [1024,16,512]
    const float* value = (const float*)d_in[2];  // [1024,16,512]
    const float* Wk    = (const float*)d_in[3];  // [8,64,512] == [512,512] row-major
    const float* bk    = (const float*)d_in[4];  // [8,64] == [512]
    float* out = (float*)d_out;                  // [1024,16,4096]

    float *wq, *wk;
    cudaGetSymbolAddress((void**)&wq, g_wq);
    cudaGetSymbolAddress((void**)&wk, g_wk);

    dim3 pg((LQ * BB) / 64, HH);  // (256, 8)
    proj_kernel<<<pg, 256>>>(query, Wk, bk, wq);
    proj_kernel<<<pg, 256>>>(key, Wk, bk, wk);

    const size_t smem = (size_t)(32 * 1024 + 32 * 64 + 64 * 68 + 32) * sizeof(float);
    cudaFuncSetAttribute(attn_kernel, cudaFuncAttributeMaxDynamicSharedMemorySize, (int)smem);
    dim3 ag(LQ / 32, HH, BB);     // (32, 8, 16)
    attn_kernel<<<ag, 256, smem>>>(value, out);
}

// round 2
// speedup vs baseline: 1.3232x; 1.3232x over previous
#include <cuda_runtime.h>
#include <math.h>

#define LQ 1024
#define BB 16
#define FF 512
#define HH 8
#define KK 64
#define TEMPS 30.0f

typedef unsigned long long ull;

// Scratch: normalized projections, layout [B][H][L][K] so each (b,h) matrix is contiguous.
__device__ float g_wq[(size_t)BB * HH * LQ * KK];
__device__ float g_wk[(size_t)BB * HH * LQ * KK];

// packed fp32x2 FMA: d = a*b + d (elementwise on the two fp32 halves)
__device__ __forceinline__ void ffma2(ull& d, ull a, ull b) {
    asm("fma.rn.f32x2 %0, %1, %2, %0;" : "+l"(d) : "l"(a), "l"(b));
}
// duplicate a float into both halves of a b64
__device__ __forceinline__ ull dup2(float x) {
    ull r;
    asm("mov.b64 %0, {%1, %1};" : "=l"(r) : "f"(x));
    return r;
}

// ---------------------------------------------------------------------------
// Kernel 1: C[M,512] = X[M,512] @ W[512,512]^T + bias, then L2-normalize each
// 64-wide head group. Tile 64x64, BK=16, 256 threads, 4x4 per thread (FFMA2).
// ---------------------------------------------------------------------------
__global__ __launch_bounds__(256) void proj_kernel(const float* __restrict__ X,
                                                   const float* __restrict__ W,
                                                   const float* __restrict__ bias,
                                                   float* __restrict__ outp) {
    __shared__ __align__(16) float As[16][68];
    __shared__ __align__(16) float Bs[16][68];
    __shared__ __align__(16) float Cs[64][68];
    __shared__ float scl[64];

    const int tid = threadIdx.x;
    const int tx = tid & 15, ty = tid >> 4;
    const int m0 = blockIdx.x * 64;
    const int h = blockIdx.y;
    const int n0 = h * 64;

    ull acc[4][2];
#pragma unroll
    for (int i = 0; i < 4; i++) { acc[i][0] = 0ull; acc[i][1] = 0ull; }

    const int lrow = tid >> 2;        // 0..63
    const int lk4 = (tid & 3) * 4;    // 0,4,8,12

    const float* Xp = X + (size_t)(m0 + lrow) * FF + lk4;
    const float* Wp = W + (size_t)(n0 + lrow) * FF + lk4;

    for (int k0 = 0; k0 < FF; k0 += 16) {
        float4 a = *(const float4*)(Xp + k0);
        float4 w = *(const float4*)(Wp + k0);
        As[lk4 + 0][lrow] = a.x; As[lk4 + 1][lrow] = a.y;
        As[lk4 + 2][lrow] = a.z; As[lk4 + 3][lrow] = a.w;
        Bs[lk4 + 0][lrow] = w.x; Bs[lk4 + 1][lrow] = w.y;
        Bs[lk4 + 2][lrow] = w.z; Bs[lk4 + 3][lrow] = w.w;
        __syncthreads();
#pragma unroll
        for (int k = 0; k < 16; k++) {
            float4 av = *(const float4*)&As[k][ty * 4];
            ulonglong2 bw = *(const ulonglong2*)&Bs[k][tx * 4];
            ull a0 = dup2(av.x), a1 = dup2(av.y), a2 = dup2(av.z), a3 = dup2(av.w);
            ffma2(acc[0][0], a0, bw.x); ffma2(acc[0][1], a0, bw.y);
            ffma2(acc[1][0], a1, bw.x); ffma2(acc[1][1], a1, bw.y);
            ffma2(acc[2][0], a2, bw.x); ffma2(acc[2][1], a2, bw.y);
            ffma2(acc[3][0], a3, bw.x); ffma2(acc[3][1], a3, bw.y);
        }
        __syncthreads();
    }

    // bias + stage tile to smem
    float bj[4];
#pragma unroll
    for (int j = 0; j < 4; j++) bj[j] = bias[n0 + tx * 4 + j];
#pragma unroll
    for (int i = 0; i < 4; i++) {
        float2 f0 = *(float2*)&acc[i][0];
        float2 f1 = *(float2*)&acc[i][1];
        Cs[ty * 4 + i][tx * 4 + 0] = f0.x + bj[0];
        Cs[ty * 4 + i][tx * 4 + 1] = f0.y + bj[1];
        Cs[ty * 4 + i][tx * 4 + 2] = f1.x + bj[2];
        Cs[ty * 4 + i][tx * 4 + 3] = f1.y + bj[3];
    }
    __syncthreads();

    // per-row (= per (q,b,h) vector) L2 norm, matching torch F.normalize eps
    if (tid < 64) {
        float ss = 0.f;
#pragma unroll 8
        for (int c = 0; c < 64; c++) {
            float v = Cs[tid][c];
            ss = fmaf(v, v, ss);
        }
        float nrm = sqrtf(ss);
        scl[tid] = 1.0f / fmaxf(nrm, 1e-12f);
    }
    __syncthreads();

#pragma unroll
    for (int i = 0; i < 4; i++) {
        int m = m0 + ty * 4 + i;
        int q = m >> 4;        // B = 16
        int b = m & 15;
        float s = scl[ty * 4 + i];
        float4 o;
        o.x = Cs[ty * 4 + i][tx * 4 + 0] * s;
        o.y = Cs[ty * 4 + i][tx * 4 + 1] * s;
        o.z = Cs[ty * 4 + i][tx * 4 + 2] * s;
        o.w = Cs[ty * 4 + i][tx * 4 + 3] * s;
        *(float4*)(outp + (((size_t)(b * HH + h) * LQ + q) * KK) + tx * 4) = o;
    }
}

// ---------------------------------------------------------------------------
// Kernel 2: attention for one (b, h, 32-row q-tile).
//   Phase A: S[32,1024] = Q[32,64] @ K^T * TEMP  (scores in smem, FFMA2)
//   Phase B: exact softmax per row
//   Phase C: O[32,512] = P @ V_b (FFMA2, 8 rows x 8 cols per thread)
// ---------------------------------------------------------------------------
__global__ __launch_bounds__(256, 1) void attn_kernel(const float* __restrict__ value,
                                                      float* __restrict__ out) {
    extern __shared__ __align__(16) float sm[];
    float* sc = sm;                       // 32*1024
    float* Qs = sm + 32 * 1024;           // 32*64
    float* Kst = Qs + 32 * 64;            // [k][s] 64*68
    float* inv = Kst + 64 * 68;           // 32

    const int tid = threadIdx.x;
    const int q0 = blockIdx.x * 32;
    const int h = blockIdx.y;
    const int b = blockIdx.z;

    const float* qbase = g_wq + ((size_t)(b * HH + h) * LQ + q0) * KK;
    const float* kbase = g_wk + (size_t)(b * HH + h) * LQ * KK;

    // load Q tile (2048 floats)
    for (int i = tid; i < 32 * 64 / 4; i += 256)
        ((float4*)Qs)[i] = ((const float4*)qbase)[i];

    const int tx = tid & 15, ty = tid >> 4;

    // ---------------- Phase A: scores ----------------
    for (int st = 0; st < 16; st++) {
        const float* kp = kbase + (size_t)st * 64 * KK;
        const int sr = tid >> 2;
        const int kb = (tid & 3) * 16;
#pragma unroll
        for (int u = 0; u < 4; u++) {
            float4 v = *(const float4*)(kp + sr * 64 + kb + u * 4);
            Kst[(kb + u * 4 + 0) * 68 + sr] = v.x;
            Kst[(kb + u * 4 + 1) * 68 + sr] = v.y;
            Kst[(kb + u * 4 + 2) * 68 + sr] = v.z;
            Kst[(kb + u * 4 + 3) * 68 + sr] = v.w;
        }
        __syncthreads();

        ull a0[2] = {0ull, 0ull}, a1[2] = {0ull, 0ull};
        const float* qr0 = Qs + (ty * 2) * 64;
        const float* qr1 = qr0 + 64;
#pragma unroll 16
        for (int k = 0; k < 64; k++) {
            ull qa = dup2(qr0[k]);
            ull qb = dup2(qr1[k]);
            ulonglong2 kv = *(const ulonglong2*)&Kst[k * 68 + tx * 4];
            ffma2(a0[0], qa, kv.x); ffma2(a0[1], qa, kv.y);
            ffma2(a1[0], qb, kv.x); ffma2(a1[1], qb, kv.y);
        }
        float2 u00 = *(float2*)&a0[0], u01 = *(float2*)&a0[1];
        float2 u10 = *(float2*)&a1[0], u11 = *(float2*)&a1[1];
        float4 s0 = make_float4(u00.x * TEMPS, u00.y * TEMPS, u01.x * TEMPS, u01.y * TEMPS);
        float4 s1 = make_float4(u10.x * TEMPS, u10.y * TEMPS, u11.x * TEMPS, u11.y * TEMPS);
        *(float4*)&sc[(ty * 2) * 1024 + st * 64 + tx * 4] = s0;
        *(float4*)&sc[(ty * 2 + 1) * 1024 + st * 64 + tx * 4] = s1;
        __syncthreads();
    }

    // ---------------- Phase B: softmax (one warp : 4 rows) ----------------
    const int w = tid >> 5, lane = tid & 31;
#pragma unroll
    for (int i = 0; i < 4; i++) {
        const int r = w * 4 + i;
        float* row = sc + r * 1024;
        float m = -1e30f;
        for (int s = lane; s < 1024; s += 32) m = fmaxf(m, row[s]);
#pragma unroll
        for (int o = 16; o; o >>= 1) m = fmaxf(m, __shfl_xor_sync(0xFFFFFFFFu, m, o));
        float sum = 0.f;
        for (int s = lane; s < 1024; s += 32) {
            float e = __expf(row[s] - m);
            row[s] = e;
            sum += e;
        }
#pragma unroll
        for (int o = 16; o; o >>= 1) sum += __shfl_xor_sync(0xFFFFFFFFu, sum, o);
        if (lane == 0) inv[r] = 1.0f / sum;
    }
    __syncthreads();

    // ---------------- Phase C: O = P @ V ----------------
    // warp w: rowg = w>>1 (8 rows), colg = w&1 (256 cols); thread: 8 rows x 8 cols.
    const int rowg = w >> 1;
    const int colg = w & 1;
    const int r0 = rowg * 8;
    const float* vbase = value + (size_t)b * FF + colg * 256 + lane * 4;

    ull acc[8][4];
#pragma unroll
    for (int i = 0; i < 8; i++)
#pragma unroll
        for (int j = 0; j < 4; j++) acc[i][j] = 0ull;

    for (int s0 = 0; s0 < LQ; s0 += 4) {
        float4 p4[8];
#pragma unroll
        for (int i = 0; i < 8; i++)
            p4[i] = *(const float4*)&sc[(r0 + i) * 1024 + s0];
#pragma unroll
        for (int u = 0; u < 4; u++) {
            const float* vp = vbase + (size_t)(s0 + u) * (BB * FF);
            ulonglong2 va = *(const ulonglong2*)vp;
            ulonglong2 vb = *(const ulonglong2*)(vp + 128);
#pragma unroll
            for (int i = 0; i < 8; i++) {
                float p = (u == 0) ? p4[i].x : (u == 1) ? p4[i].y : (u == 2) ? p4[i].z : p4[i].w;
                ull pp = dup2(p);
                ffma2(acc[i][0], pp, va.x);
                ffma2(acc[i][1], pp, va.y);
                ffma2(acc[i][2], pp, vb.x);
                ffma2(acc[i][3], pp, vb.y);
            }
        }
    }

#pragma unroll
    for (int i = 0; i < 8; i++) {
        const int q = q0 + r0 + i;
        const float iv = inv[r0 + i];
        float* op = out + ((size_t)q * BB + b) * (HH * FF) + h * FF + colg * 256 + lane * 4;
        float2 f0 = *(float2*)&acc[i][0];
        float2 f1 = *(float2*)&acc[i][1];
        float2 f2 = *(float2*)&acc[i][2];
        float2 f3 = *(float2*)&acc[i][3];
        float4 o0 = make_float4(f0.x * iv, f0.y * iv, f1.x * iv, f1.y * iv);
        float4 o1 = make_float4(f2.x * iv, f2.y * iv, f3.x * iv, f3.y * iv);
        *(float4*)(op) = o0;
        *(float4*)(op + 128) = o1;
    }
}

// ---------------------------------------------------------------------------
extern "C" void kernel_launch(void* const* d_in, const int* in_sizes, int n_in,
                              void* d_out, int out_size) {
    const float* query = (const float*)d_in[0];  // [1024,16,512]
    const float* key   = (const float*)d_in[1];  // [1024,16,512]
    const float* value = (const float*)d_in[2];  // [1024,16,512]
    const float* Wk    = (const float*)d_in[3];  // [8,64,512] == [512,512] row-major
    const float* bk    = (const float*)d_in[4];  // [8,64] == [512]
    float* out = (float*)d_out;                  // [1024,16,4096]

    float *wq, *wk;
    cudaGetSymbolAddress((void**)&wq, g_wq);
    cudaGetSymbolAddress((void**)&wk, g_wk);

    dim3 pg((LQ * BB) / 64, HH);  // (256, 8)
    proj_kernel<<<pg, 256>>>(query, Wk, bk, wq);
    proj_kernel<<<pg, 256>>>(key, Wk, bk, wk);

    const size_t smem = (size_t)(32 * 1024 + 32 * 64 + 64 * 68 + 32) * sizeof(float);
    cudaFuncSetAttribute(attn_kernel, cudaFuncAttributeMaxDynamicSharedMemorySize, (int)smem);
    dim3 ag(LQ / 32, HH, BB);     // (32, 8, 16)
    attn_kernel<<<ag, 256, smem>>>(value, out);
}